// round 14
// baseline (speedup 1.0000x reference)
#include <cuda_runtime.h>

// B=128, N=1024. out[b,k] = a[b,j] - a[b,i], strict upper triangle (j>i),
// row-major pair order. Row i (len 1023-i) starts at off(i) = i*(2047-i)/2.
//
// One ROW-PAIR per warp (pair p = row p + row 1022-p = exactly 1024 outputs);
// 4 pairs per warp (32 pairs/block, grid 16x128) to amortize smem staging.
// R14: rolled warp-stride loop with 4 pointer-bumped batches per iteration
// (MLP 4: all 4 LDS.128 issue before the 4 STG.128). Combines R13's small
// register footprint (rolled, bumped addresses) with R9's deep MLP, which
// was empirically the strongest lever on this write-bound stream.

constexpr int N_ELEM  = 1024;
constexpr int M_PAIRS = N_ELEM * (N_ELEM - 1) / 2;   // 523776
constexpr int THREADS = 256;                          // 8 warps
constexpr int PAIRS_PER_WARP  = 4;
constexpr int PAIRS_PER_BLOCK = 8 * PAIRS_PER_WARP;   // 32
constexpr int PITCH   = N_ELEM + 4;                   // 16B-aligned copy pitch

__device__ __forceinline__ int row_off(int i) {
    return (i * (2047 - i)) >> 1;                     // exact (product even)
}

__device__ __forceinline__ void process_row(int i, const float* __restrict__ sh,
                                            float* __restrict__ outb, int lane) {
    const int start = row_off(i);
    const int len   = 1023 - i;
    const int end   = start + len;
    const float ai  = sh[i];                          // broadcast LDS

    const int astart = (start + 3) & ~3;
    const int aend   = end & ~3;

    // Head scalars (<=3 lanes)
    const int head_n = min(astart, end) - start;
    if (lane < head_n)
        outb[start + lane] = sh[i + 1 + lane] - ai;
    // Tail scalars (<=3 lanes)
    const int tstart = max(aend, astart);
    const int tail_n = end - tstart;
    if (lane < tail_n)
        outb[tstart + lane] = sh[i + 1 + (tstart - start) + lane] - ai;

    int n4 = (aend - astart) >> 2;
    if (n4 < 0) n4 = 0;
    const int jbase = i + 1 + (astart - start);
    const int r     = jbase & 3;
    const float* __restrict__ src = sh + r * PITCH + (jbase - r);
    float* __restrict__ dst = outb + astart;

    // Rolled warp-stride loop, 4 batches per iteration (MLP 4).
    // Long row: n4 <= 255 -> 2 iterations. Short row: n4 <= 128 -> 1 iter.
    #pragma unroll 1
    for (int q = lane; q < n4; q += 128) {
        float4 v[4];
        bool pr[4];
        #pragma unroll
        for (int u = 0; u < 4; u++) {
            const int qq = q + 32 * u;
            pr[u] = qq < n4;
            if (pr[u])
                v[u] = *reinterpret_cast<const float4*>(src + (qq << 2));
        }
        #pragma unroll
        for (int u = 0; u < 4; u++) {
            const int qq = q + 32 * u;
            if (pr[u])
                *reinterpret_cast<float4*>(dst + (qq << 2)) =
                    make_float4(v[u].x - ai, v[u].y - ai, v[u].z - ai, v[u].w - ai);
        }
    }
}

__global__ __launch_bounds__(THREADS)
void relpos_kernel(const float* __restrict__ in, float* __restrict__ out) {
    // 4 shifted copies: sh[r*PITCH + m] = a[m + r]
    __shared__ float sh[4 * PITCH];

    const int b = blockIdx.y;
    const float* a = in + (size_t)b * N_ELEM;

    // Stage input + build shifted copies (one float4 per thread).
    {
        const float4 v = reinterpret_cast<const float4*>(a)[threadIdx.x];
        const int idx = threadIdx.x * 4;
        const float vv[4] = {v.x, v.y, v.z, v.w};
        #pragma unroll
        for (int e = 0; e < 4; e++) {
            const int x = idx + e;
            const float val = vv[e];
            #pragma unroll
            for (int r = 0; r < 4; r++) {
                const int m = x - r;
                if (m >= 0) sh[r * PITCH + m] = val;
            }
        }
    }
    __syncthreads();

    float* outb = out + (size_t)b * M_PAIRS;
    const int warp = threadIdx.x >> 5;
    const int lane = threadIdx.x & 31;

    #pragma unroll 1
    for (int sub = 0; sub < PAIRS_PER_WARP; sub++) {
        const int p = blockIdx.x * PAIRS_PER_BLOCK + warp + 8 * sub; // 0..511
        process_row(p, sh, outb, lane);                // long row (len 1023-p)
        if (p < 511)
            process_row(1022 - p, sh, outb, lane);     // short row (len p+1)
    }
}

extern "C" void kernel_launch(void* const* d_in, const int* in_sizes, int n_in,
                              void* d_out, int out_size) {
    const float* in = (const float*)d_in[0];
    float* out = (float*)d_out;
    const int B = in_sizes[0] / N_ELEM;               // 128

    dim3 grid(512 / PAIRS_PER_BLOCK, B);              // (16, 128)
    relpos_kernel<<<grid, THREADS>>>(in, out);
}